// round 6
// baseline (speedup 1.0000x reference)
#include <cuda_runtime.h>
#include <cuda_fp16.h>
#include <math.h>
#include <cstdint>

#define NB 4
#define NC 256
#define HW 4096
#define NHEADS 4
#define HD 64

// Scratch (allocation-free rule: __device__ globals)
__device__ float g_qkv[(size_t)NB * 3 * NC * HW]; // [b][o(768)][hw]
__device__ float g_att[(size_t)NB * NC * HW];     // [b][c][hw]

// ---------------- helpers ----------------
__device__ __forceinline__ float ex2f(float x) {
    float y;
    asm("ex2.approx.f32 %0, %1;" : "=f"(y) : "f"(x));
    return y;
}
// pack two fp32 -> f16x2 (lo in bits [15:0])
__device__ __forceinline__ unsigned pkhf2(float lo, float hi) {
    unsigned r;
    asm("cvt.rn.f16x2.f32 %0, %1, %2;" : "=r"(r) : "f"(hi), "f"(lo));
    return r;
}
// tf32 mma (GEMMs, verified)
__device__ __forceinline__ void mma_tf32(float c[4], const float a[4], float b0,
                                         float b1) {
    asm volatile(
        "mma.sync.aligned.m16n8k8.row.col.f32.tf32.tf32.f32 "
        "{%0,%1,%2,%3}, {%4,%5,%6,%7}, {%8,%9}, {%0,%1,%2,%3};"
        : "+f"(c[0]), "+f"(c[1]), "+f"(c[2]), "+f"(c[3])
        : "r"(__float_as_uint(a[0])), "r"(__float_as_uint(a[1])),
          "r"(__float_as_uint(a[2])), "r"(__float_as_uint(a[3])),
          "r"(__float_as_uint(b0)), "r"(__float_as_uint(b1)));
}
// fp16 mma m16n8k16, fp32 accumulate
__device__ __forceinline__ void mma_f16(float c[4], const unsigned a[4],
                                        unsigned b0, unsigned b1) {
    asm volatile(
        "mma.sync.aligned.m16n8k16.row.col.f32.f16.f16.f32 "
        "{%0,%1,%2,%3}, {%4,%5,%6,%7}, {%8,%9}, {%0,%1,%2,%3};"
        : "+f"(c[0]), "+f"(c[1]), "+f"(c[2]), "+f"(c[3])
        : "r"(a[0]), "r"(a[1]), "r"(a[2]), "r"(a[3]), "r"(b0), "r"(b1));
}
__device__ __forceinline__ void cpa16(void* dst, const void* src) {
    unsigned d = (unsigned)__cvta_generic_to_shared(dst);
    asm volatile("cp.async.cg.shared.global [%0], [%1], 16;" ::"r"(d), "l"(src));
}
#define CP_COMMIT asm volatile("cp.async.commit_group;")
#define CP_WAIT(n) asm volatile("cp.async.wait_group %0;" ::"n"(n))

// ================ tf32 tensor-core GEMM (unchanged, verified) ================
#define GA_PITCH 36
#define GB_PITCH 136
#define GA_FLOATS (128 * GA_PITCH)
#define GB_FLOATS (32 * GB_PITCH)
#define GEMM_SMEM ((2 * GA_FLOATS + 2 * GB_FLOATS) * sizeof(float))

template <int M, bool EPI>
__global__ __launch_bounds__(256, 2) void gemm_tc(const float* __restrict__ W,
                                                  const float* __restrict__ X,
                                                  const float* __restrict__ bias,
                                                  const float* __restrict__ R,
                                                  float* __restrict__ Y) {
    extern __shared__ float sm[];
    float* sA = sm;
    float* sB = sm + 2 * GA_FLOATS;
    const int b = blockIdx.z;
    const float* Xb = X + (size_t)b * 256 * HW;
    float* Yb = Y + (size_t)b * M * HW;
    const float* Rb = EPI ? (R + (size_t)b * M * HW) : nullptr;
    const int o0 = blockIdx.y * 128;
    const int i0 = blockIdx.x * 128;
    const int tid = threadIdx.x, warp = tid >> 5, lane = tid & 31;
    const int g = lane >> 2, t = lane & 3;
    const int wm = (warp >> 1) * 32, wn = (warp & 1) * 64;

    float acc[2][8][4];
#pragma unroll
    for (int mt = 0; mt < 2; mt++)
#pragma unroll
        for (int nt = 0; nt < 8; nt++)
#pragma unroll
            for (int r = 0; r < 4; r++) acc[mt][nt][r] = 0.f;

    auto stage = [&](int ch, int buf) {
        float* dA = sA + buf * GA_FLOATS;
        float* dB = sB + buf * GB_FLOATS;
        const int c0 = ch * 32;
#pragma unroll
        for (int l = 0; l < 4; l++) {
            int idx = tid + l * 256;
            int row = idx >> 3, seg = (idx & 7) * 4;
            cpa16(dA + row * GA_PITCH + seg,
                  W + (size_t)(o0 + row) * 256 + c0 + seg);
        }
#pragma unroll
        for (int l = 0; l < 4; l++) {
            int idx = tid + l * 256;
            int row = idx >> 5, seg = (idx & 31) * 4;
            cpa16(dB + row * GB_PITCH + seg,
                  Xb + (size_t)(c0 + row) * HW + i0 + seg);
        }
    };

    stage(0, 0);
    CP_COMMIT;
    for (int ch = 0; ch < 8; ch++) {
        if (ch < 7) {
            stage(ch + 1, (ch + 1) & 1);
            CP_COMMIT;
            CP_WAIT(1);
        } else {
            CP_WAIT(0);
        }
        __syncthreads();
        const float* bA = sA + (ch & 1) * GA_FLOATS;
        const float* bB = sB + (ch & 1) * GB_FLOATS;
#pragma unroll
        for (int ks = 0; ks < 4; ks++) {
            float a[2][4];
#pragma unroll
            for (int mt = 0; mt < 2; mt++) {
                int r0 = wm + mt * 16 + g;
                a[mt][0] = bA[r0 * GA_PITCH + ks * 8 + t];
                a[mt][1] = bA[(r0 + 8) * GA_PITCH + ks * 8 + t];
                a[mt][2] = bA[r0 * GA_PITCH + ks * 8 + t + 4];
                a[mt][3] = bA[(r0 + 8) * GA_PITCH + ks * 8 + t + 4];
            }
#pragma unroll
            for (int nt = 0; nt < 8; nt++) {
                float b0 = bB[(ks * 8 + t) * GB_PITCH + wn + nt * 8 + g];
                float b1 = bB[(ks * 8 + t + 4) * GB_PITCH + wn + nt * 8 + g];
                mma_tf32(acc[0][nt], a[0], b0, b1);
                mma_tf32(acc[1][nt], a[1], b0, b1);
            }
        }
        __syncthreads();
    }
#pragma unroll
    for (int mt = 0; mt < 2; mt++) {
#pragma unroll
        for (int nt = 0; nt < 8; nt++) {
            int row0 = o0 + wm + mt * 16 + g;
            int col = i0 + wn + nt * 8 + 2 * t;
            size_t a0 = (size_t)row0 * HW + col;
            size_t a1 = (size_t)(row0 + 8) * HW + col;
            float2 v0 = make_float2(acc[mt][nt][0], acc[mt][nt][1]);
            float2 v1 = make_float2(acc[mt][nt][2], acc[mt][nt][3]);
            if (EPI) {
                float add0 = bias[row0], add1 = bias[row0 + 8];
                float2 r0 = *(const float2*)&Rb[a0];
                float2 r1 = *(const float2*)&Rb[a1];
                v0.x += add0 + r0.x; v0.y += add0 + r0.y;
                v1.x += add1 + r1.x; v1.y += add1 + r1.y;
            }
            *(float2*)&Yb[a0] = v0;
            *(float2*)&Yb[a1] = v1;
        }
    }
}

// ================ fp16 mma flash attention ================
// Grid (32, 16), 256 threads = 8 warps. Warp w owns Q rows [w*16, w*16+16).
// SMEM: fp32 staging sKf/sVf [2][64][132] (cp.async double buffer),
//       packed-half2 tiles sK2 [32dp][136] (pair along d), sV2 [64d][68] (pair along j).
#define KF_FLOATS (64 * 132)
#define OFF_KF 0
#define OFF_VF (2 * KF_FLOATS * 4)
#define OFF_K2 (4 * KF_FLOATS * 4)
#define OFF_V2 (OFF_K2 + 32 * 136 * 4)
#define ATT_SMEM (OFF_V2 + 64 * 68 * 4)

__global__ __launch_bounds__(256, 1) void attn_k() {
    extern __shared__ char smc[];
    float* sKf = (float*)(smc + OFF_KF);   // [2][64][132]
    float* sVf = (float*)(smc + OFF_VF);   // [2][64][132]
    unsigned* sK2 = (unsigned*)(smc + OFF_K2);  // [32][136] half2(K[2dp][j],K[2dp+1][j])
    unsigned* sV2 = (unsigned*)(smc + OFF_V2);  // [64][68]  half2(V[d][2jp],V[d][2jp+1])

    const int bh = blockIdx.y;
    const int b = bh >> 2, h = bh & 3;
    const float* Qb = g_qkv + ((size_t)b * 768 + h * 64) * HW;
    const float* Kb = Qb + (size_t)256 * HW;
    const float* Vb = Qb + (size_t)512 * HW;
    const int i0 = blockIdx.x * 128;
    const int tid = threadIdx.x;
    const int warp = tid >> 5, lane = tid & 31;
    const int g = lane >> 2, t = lane & 3;
    const int iw = warp * 16;

    const float QSCALE = 0.125f * 1.4426950408889634f;  // d^-0.5 * log2(e)

    auto stage_kv = [&](int kt, int buf) {
        const float* Kt = Kb + (size_t)kt * 128;
        const float* Vt = Vb + (size_t)kt * 128;
        float* dK = sKf + buf * KF_FLOATS;
        float* dV = sVf + buf * KF_FLOATS;
        for (int e = tid * 4; e < 64 * 128; e += 1024) {
            int d = e >> 7, j = e & 127;
            cpa16(dK + d * 132 + j, Kt + (size_t)d * HW + j);
            cpa16(dV + d * 132 + j, Vt + (size_t)d * HW + j);
        }
    };

    // prefetch tile 0 into buf 0; stage Q (fp32) into buf-1 region meanwhile
    stage_kv(0, 0);
    CP_COMMIT;

    float* sQst = sKf + KF_FLOATS;  // buf 1 region, free until tile 1 staging
    for (int e = tid * 4; e < 64 * 128; e += 1024) {
        int d = e >> 7, i = e & 127;
        *(float4*)&sQst[d * 132 + i] = *(const float4*)&Qb[(size_t)d * HW + i0 + i];
    }
    __syncthreads();

    // persistent Q fragments (fp16, scale folded): qa[ks][0..3]
    // a0={Q[g][16ks+2t,+1]}, a1=rows g+8, a2=cols +8, a3=rows g+8 cols +8
    unsigned qa[4][4];
#pragma unroll
    for (int ks = 0; ks < 4; ks++) {
        int d0 = ks * 16 + 2 * t;
        float q00 = sQst[(d0)*132 + iw + g] * QSCALE;
        float q01 = sQst[(d0 + 1) * 132 + iw + g] * QSCALE;
        float q10 = sQst[(d0)*132 + iw + g + 8] * QSCALE;
        float q11 = sQst[(d0 + 1) * 132 + iw + g + 8] * QSCALE;
        float q20 = sQst[(d0 + 8) * 132 + iw + g] * QSCALE;
        float q21 = sQst[(d0 + 9) * 132 + iw + g] * QSCALE;
        float q30 = sQst[(d0 + 8) * 132 + iw + g + 8] * QSCALE;
        float q31 = sQst[(d0 + 9) * 132 + iw + g + 8] * QSCALE;
        qa[ks][0] = pkhf2(q00, q01);
        qa[ks][1] = pkhf2(q10, q11);
        qa[ks][2] = pkhf2(q20, q21);
        qa[ks][3] = pkhf2(q30, q31);
    }
    __syncthreads();  // all threads done with sQst before tile-1 staging

    float o[8][4];
#pragma unroll
    for (int dt = 0; dt < 8; dt++)
#pragma unroll
        for (int r = 0; r < 4; r++) o[dt][r] = 0.f;
    float m0 = -INFINITY, m1 = -INFINITY, l0 = 0.f, l1 = 0.f;

    for (int kt = 0; kt < 32; kt++) {
        if (kt + 1 < 32) {
            stage_kv(kt + 1, (kt + 1) & 1);
            CP_COMMIT;
            CP_WAIT(1);
        } else {
            CP_WAIT(0);
        }
        __syncthreads();
        const float* fK = sKf + (kt & 1) * KF_FLOATS;
        const float* fV = sVf + (kt & 1) * KF_FLOATS;

        // ---- convert K: pack pairs along d -> sK2[dp][j] ----
        {
            int dp = tid >> 3, j0 = (tid & 7) << 4;
            const float* r0 = fK + (2 * dp) * 132 + j0;
            const float* r1 = fK + (2 * dp + 1) * 132 + j0;
            unsigned* dst = sK2 + dp * 136 + j0;
#pragma unroll
            for (int jj = 0; jj < 16; jj++) dst[jj] = pkhf2(r0[jj], r1[jj]);
        }
        // ---- convert V: pack pairs along j -> sV2[d][jp] ----
        {
            int d = tid >> 2, jp0 = (tid & 3) << 4;
            const float* r = fV + d * 132 + 2 * jp0;
            unsigned* dst = sV2 + d * 68 + jp0;
#pragma unroll
            for (int pp = 0; pp < 16; pp++)
                dst[pp] = pkhf2(r[2 * pp], r[2 * pp + 1]);
        }
        __syncthreads();

        // ---- S = Q K^T : 16 n8-tiles, k over d (4 k16-steps) ----
        float c[16][4];
#pragma unroll
        for (int jt = 0; jt < 16; jt++)
#pragma unroll
            for (int r = 0; r < 4; r++) c[jt][r] = 0.f;
#pragma unroll
        for (int ks = 0; ks < 4; ks++) {
            const unsigned* kb0 = sK2 + (8 * ks + t) * 136;
            const unsigned* kb1 = sK2 + (8 * ks + t + 4) * 136;
#pragma unroll
            for (int jt = 0; jt < 16; jt++)
                mma_f16(c[jt], qa[ks], kb0[jt * 8 + g], kb1[jt * 8 + g]);
        }

        // ---- online softmax (log2 domain) ----
        float mx0 = c[0][0], mx1 = c[0][2];
#pragma unroll
        for (int jt = 0; jt < 16; jt++) {
            mx0 = fmaxf(mx0, fmaxf(c[jt][0], c[jt][1]));
            mx1 = fmaxf(mx1, fmaxf(c[jt][2], c[jt][3]));
        }
        mx0 = fmaxf(mx0, __shfl_xor_sync(0xffffffffu, mx0, 1));
        mx0 = fmaxf(mx0, __shfl_xor_sync(0xffffffffu, mx0, 2));
        mx1 = fmaxf(mx1, __shfl_xor_sync(0xffffffffu, mx1, 1));
        mx1 = fmaxf(mx1, __shfl_xor_sync(0xffffffffu, mx1, 2));
        float nm0 = fmaxf(m0, mx0), nm1 = fmaxf(m1, mx1);
        float r0 = ex2f(m0 - nm0), r1 = ex2f(m1 - nm1);
        float rs0 = 0.f, rs1 = 0.f;
#pragma unroll
        for (int jt = 0; jt < 16; jt++) {
            c[jt][0] = ex2f(c[jt][0] - nm0);
            c[jt][1] = ex2f(c[jt][1] - nm0);
            c[jt][2] = ex2f(c[jt][2] - nm1);
            c[jt][3] = ex2f(c[jt][3] - nm1);
            rs0 += c[jt][0] + c[jt][1];
            rs1 += c[jt][2] + c[jt][3];
        }
        rs0 += __shfl_xor_sync(0xffffffffu, rs0, 1);
        rs0 += __shfl_xor_sync(0xffffffffu, rs0, 2);
        rs1 += __shfl_xor_sync(0xffffffffu, rs1, 1);
        rs1 += __shfl_xor_sync(0xffffffffu, rs1, 2);
        l0 = l0 * r0 + rs0;
        l1 = l1 * r1 + rs1;
        m0 = nm0; m1 = nm1;
#pragma unroll
        for (int dt = 0; dt < 8; dt++) {
            o[dt][0] *= r0; o[dt][1] *= r0;
            o[dt][2] *= r1; o[dt][3] *= r1;
        }

        // ---- O += P V : P stays in registers (C frag == A frag layout) ----
#pragma unroll
        for (int ks2 = 0; ks2 < 8; ks2++) {
            unsigned pa[4];
            pa[0] = pkhf2(c[2 * ks2][0], c[2 * ks2][1]);
            pa[1] = pkhf2(c[2 * ks2][2], c[2 * ks2][3]);
            pa[2] = pkhf2(c[2 * ks2 + 1][0], c[2 * ks2 + 1][1]);
            pa[3] = pkhf2(c[2 * ks2 + 1][2], c[2 * ks2 + 1][3]);
#pragma unroll
            for (int dt = 0; dt < 8; dt++) {
                const unsigned* vb = sV2 + (dt * 8 + g) * 68 + 8 * ks2;
                mma_f16(o[dt], pa, vb[t], vb[t + 4]);
            }
        }
        __syncthreads();  // sK2/sV2 safe to overwrite next tile
    }

    // ---- epilogue: O/l -> g_att[b][h*64+d][i0+i] ----
    float inv0 = 1.f / l0, inv1 = 1.f / l1;
    const size_t cb = ((size_t)b * 256 + h * 64);
#pragma unroll
    for (int dt = 0; dt < 8; dt++) {
        int d0 = dt * 8 + 2 * t;
        size_t r0a = (cb + d0) * HW + i0 + iw + g;
        size_t r1a = (cb + d0 + 1) * HW + i0 + iw + g;
        g_att[r0a] = o[dt][0] * inv0;
        g_att[r1a] = o[dt][1] * inv0;
        g_att[r0a + 8] = o[dt][2] * inv1;
        g_att[r1a + 8] = o[dt][3] * inv1;
    }
}

// ---------------- launch ----------------
extern "C" void kernel_launch(void* const* d_in, const int* in_sizes, int n_in,
                              void* d_out, int out_size) {
    (void)in_sizes; (void)n_in; (void)out_size;
    const float* x     = (const float*)d_in[0];
    const float* w_qkv = (const float*)d_in[1];
    const float* w_out = (const float*)d_in[2];
    const float* b_out = (const float*)d_in[3];
    float* out = (float*)d_out;

    float* qkv_p = nullptr;
    float* att_p = nullptr;
    cudaGetSymbolAddress((void**)&qkv_p, g_qkv);
    cudaGetSymbolAddress((void**)&att_p, g_att);

    cudaFuncSetAttribute(gemm_tc<768, false>,
                         cudaFuncAttributeMaxDynamicSharedMemorySize,
                         (int)GEMM_SMEM);
    cudaFuncSetAttribute(gemm_tc<256, true>,
                         cudaFuncAttributeMaxDynamicSharedMemorySize,
                         (int)GEMM_SMEM);
    cudaFuncSetAttribute(attn_k, cudaFuncAttributeMaxDynamicSharedMemorySize,
                         (int)ATT_SMEM);

    gemm_tc<768, false><<<dim3(32, 6, 4), 256, GEMM_SMEM>>>(w_qkv, x, nullptr,
                                                            nullptr, qkv_p);
    attn_k<<<dim3(32, 16), 256, ATT_SMEM>>>();
    gemm_tc<256, true><<<dim3(32, 2, 4), 256, GEMM_SMEM>>>(w_out, att_p, b_out,
                                                           x, out);
}